// round 8
// baseline (speedup 1.0000x reference)
#include <cuda_runtime.h>
#include <cstdint>

#define NB   1024
#define NPG  64
#define EPG  1024
#define NEPG 256
#define NN   (NB*NPG)
#define NEDGE (NB*EPG)
#define EMB  64
#define HID  128
#define NCAT 100
#define NET  4
#define NOUT 101
#define OUTW (1 + NPG*NOUT + NEPG)   // 6721
#define STR  132                      // feature tile stride (floats)
#define ASTR 66                       // alpha tile stride (floats)

typedef unsigned int u32;
typedef unsigned short u16;
typedef unsigned char u8;

// ---------------- device scratch ----------------
__device__ float g_P1[NCAT*HID];
__device__ float g_ea[2][NET];
__device__ u8    g_sedge[NEDGE];        // per-graph dst-sorted: src | attr<<6
__device__ u16   g_soff[NB*NPG];        // per-graph CSR start offsets
__device__ float g_hw[(size_t)NN*HID];  // K1 output (h1 @ c2_w)
__device__ uint4 g_Bf[4][4096];         // fragment-order split-bf16 weights

// ---------------- helpers ----------------
__device__ __forceinline__ u32 bfpack(float lo, float hi) {
    u32 r; asm("cvt.rn.bf16x2.f32 %0, %1, %2;" : "=r"(r) : "f"(hi), "f"(lo)); return r;
}
__device__ __forceinline__ void split_pair(float x0, float x1, u32& ph, u32& pl) {
    ph = bfpack(x0, x1);
    float h0 = __uint_as_float(ph << 16);
    float h1 = __uint_as_float(ph & 0xFFFF0000u);
    pl = bfpack(x0 - h0, x1 - h1);
}
__device__ __forceinline__ void mma16816(float* c, const u32* a, u32 b0, u32 b1) {
    asm volatile(
        "mma.sync.aligned.m16n8k16.row.col.f32.bf16.bf16.f32 "
        "{%0,%1,%2,%3}, {%4,%5,%6,%7}, {%8,%9}, {%0,%1,%2,%3};"
        : "+f"(c[0]), "+f"(c[1]), "+f"(c[2]), "+f"(c[3])
        : "r"(a[0]), "r"(a[1]), "r"(a[2]), "r"(a[3]), "r"(b0), "r"(b1));
}

// 64x128 @ 128x{128|101} split-bf16; A f32 smem (stride STR), B fragments global.
__device__ __forceinline__ void mma_block(const float* __restrict__ sA,
                                          const uint4* __restrict__ Bf,
                                          int wid, int lane, float acc[8][4]) {
    int rt = wid & 3, ch = wid >> 2;
    int r0 = rt * 16 + (lane >> 2);
    int kc = (lane & 3) * 2;
    const float* pr0 = sA + r0 * STR;
    const float* pr8 = sA + (r0 + 8) * STR;
    #pragma unroll
    for (int nt = 0; nt < 8; nt++)
        #pragma unroll
        for (int j = 0; j < 4; j++) acc[nt][j] = 0.f;
    #pragma unroll
    for (int ks = 0; ks < 8; ks++) {
        int k0 = ks * 16 + kc;
        float2 v00 = *(const float2*)(pr0 + k0);
        float2 v10 = *(const float2*)(pr8 + k0);
        float2 v01 = *(const float2*)(pr0 + k0 + 8);
        float2 v11 = *(const float2*)(pr8 + k0 + 8);
        u32 ah[4], al[4];
        split_pair(v00.x, v00.y, ah[0], al[0]);
        split_pair(v10.x, v10.y, ah[1], al[1]);
        split_pair(v01.x, v01.y, ah[2], al[2]);
        split_pair(v11.x, v11.y, ah[3], al[3]);
        const uint4* bp = Bf + (ks << 9) + (ch << 8) + lane;
        #pragma unroll
        for (int nt = 0; nt < 8; nt++) {
            uint4 b = bp[nt << 5];
            mma16816(acc[nt], ah, b.x, b.y);
            mma16816(acc[nt], al, b.x, b.y);
            mma16816(acc[nt], ah, b.z, b.w);
        }
    }
}

// aggregation GEMM: out[64x128] = alpha[64x64] @ h[64x128], both f32 in smem
__device__ __forceinline__ void mma_agg(const float* __restrict__ sAl,
                                        const float* __restrict__ shh,
                                        int wid, int lane, float acc[8][4]) {
    int rt = wid & 3, ch = wid >> 2;
    int r0 = rt * 16 + (lane >> 2);
    int kc = (lane & 3) * 2;
    int nb = ch * 64 + (lane >> 2);
    #pragma unroll
    for (int nt = 0; nt < 8; nt++)
        #pragma unroll
        for (int j = 0; j < 4; j++) acc[nt][j] = 0.f;
    #pragma unroll
    for (int ks = 0; ks < 4; ks++) {
        int k0 = ks * 16 + kc;
        float2 a00 = *(const float2*)(sAl + r0 * ASTR + k0);
        float2 a10 = *(const float2*)(sAl + (r0 + 8) * ASTR + k0);
        float2 a01 = *(const float2*)(sAl + r0 * ASTR + k0 + 8);
        float2 a11 = *(const float2*)(sAl + (r0 + 8) * ASTR + k0 + 8);
        u32 ah[4], al[4];
        split_pair(a00.x, a00.y, ah[0], al[0]);
        split_pair(a10.x, a10.y, ah[1], al[1]);
        split_pair(a01.x, a01.y, ah[2], al[2]);
        split_pair(a11.x, a11.y, ah[3], al[3]);
        const float* bk0 = shh + k0 * STR;
        #pragma unroll
        for (int nt = 0; nt < 8; nt++) {
            int n = nb + nt * 8;
            float f0 = bk0[n];
            float f1 = bk0[STR + n];
            float f8 = bk0[8 * STR + n];
            float f9 = bk0[9 * STR + n];
            u32 bh0, bl0, bh1, bl1;
            split_pair(f0, f1, bh0, bl0);
            split_pair(f8, f9, bh1, bl1);
            mma16816(acc[nt], ah, bh0, bh1);
            mma16816(acc[nt], al, bh0, bh1);
            mma16816(acc[nt], ah, bl0, bl1);
        }
    }
}

// ---------------- attention: build dense alpha matrix ----------------
__device__ __forceinline__ void attn_alpha(
    const float* __restrict__ shh, float* __restrict__ salpha,
    const u16* __restrict__ soff, const u8* __restrict__ sedge,
    const float* shas, const float* shad, const float* shea,
    float* shs, float* shd, int tid)
{
    int lane = tid & 31, w = tid >> 5;

    // per-node attention scalars
    for (int r = w; r < NPG; r += 8) {
        float ss = 0.f, dd = 0.f;
        #pragma unroll
        for (int u = 0; u < 4; u++) {
            int c = lane + 32 * u;
            float hv = shh[r * STR + c];
            ss += hv * shas[c]; dd += hv * shad[c];
        }
        #pragma unroll
        for (int o = 16; o; o >>= 1) {
            ss += __shfl_down_sync(0xffffffffu, ss, o);
            dd += __shfl_down_sync(0xffffffffu, dd, o);
        }
        if (lane == 0) { shs[r] = ss; shd[r] = dd; }
    }
    __syncthreads();

    // warp per dst: max, den, scatter alpha
    for (int dl = w; dl < NPG; dl += 8) {
        int st = soff[dl];
        int en = (dl < NPG - 1) ? soff[dl + 1] : EPG;
        float db = shd[dl];
        float m = -1e30f;
        for (int j = st + lane; j < en; j += 32) {
            u32 p = sedge[j];
            float lg = shs[p & 63] + db + shea[p >> 6];
            lg = lg > 0.f ? lg : 0.2f * lg;
            m = fmaxf(m, lg);
        }
        #pragma unroll
        for (int o = 16; o; o >>= 1) m = fmaxf(m, __shfl_xor_sync(0xffffffffu, m, o));
        float den = 0.f;
        for (int j = st + lane; j < en; j += 32) {
            u32 p = sedge[j];
            float lg = shs[p & 63] + db + shea[p >> 6];
            lg = lg > 0.f ? lg : 0.2f * lg;
            den += expf(lg - m);
        }
        #pragma unroll
        for (int o = 16; o; o >>= 1) den += __shfl_xor_sync(0xffffffffu, den, o);
        float inv = 1.f / (den + 1e-16f);
        for (int j = st + lane; j < en; j += 32) {
            u32 p = sedge[j];
            float lg = shs[p & 63] + db + shea[p >> 6];
            lg = lg > 0.f ? lg : 0.2f * lg;
            atomicAdd(&salpha[dl * ASTR + (p & 63)], expf(lg - m) * inv);
        }
    }
}

// ---------------- prep kernels ----------------
__global__ void prep_main(const float* __restrict__ node_tab,
                          const float* __restrict__ edge_tab,
                          const float* __restrict__ c1_w,
                          const float* __restrict__ c1_we,
                          const float* __restrict__ c1_ae,
                          const float* __restrict__ c2_we,
                          const float* __restrict__ c2_ae) {
    __shared__ float red[HID];
    int bid = blockIdx.x, tid = threadIdx.x;
    if (bid < NCAT) {
        float acc = 0.f;
        #pragma unroll 8
        for (int k = 0; k < EMB; k++) acc += node_tab[bid*EMB + k] * c1_w[k*HID + tid];
        g_P1[bid*HID + tid] = acc;
    } else {
        for (int combo = 0; combo < 2*NET; combo++) {
            int layer = combo >> 2, t = combo & 3;
            const float* We = layer ? c2_we : c1_we;
            const float* ae = layer ? c2_ae : c1_ae;
            float acc = 0.f;
            #pragma unroll 8
            for (int k = 0; k < EMB; k++) acc += edge_tab[t*EMB + k] * We[k*HID + tid];
            red[tid] = acc * ae[tid];
            __syncthreads();
            if (tid < 32) {
                float s = red[tid] + red[tid+32] + red[tid+64] + red[tid+96];
                #pragma unroll
                for (int o = 16; o; o >>= 1) s += __shfl_down_sync(0xffffffffu, s, o);
                if (tid == 0) g_ea[layer][t] = s;
            }
            __syncthreads();
        }
    }
}

__global__ void prep_w(const float* __restrict__ w0, const float* __restrict__ w1,
                       const float* __restrict__ w2, const float* __restrict__ w3) {
    int b = blockIdx.x, tid = threadIdx.x;
    const float* W = (b == 0) ? w0 : (b == 1) ? w1 : (b == 2) ? w2 : w3;
    int CW = (b == 3) ? NOUT : HID;
    for (int i = tid; i < 4096; i += 256) {
        int ks = i >> 9, rest = i & 511;
        int nt = rest >> 5, l = rest & 31;
        int k = ks * 16 + (l & 3) * 2;
        int n = nt * 8 + (l >> 2);
        float w00=0.f, w01=0.f, w10=0.f, w11=0.f;
        if (n < CW) {
            w00 = W[(size_t)k * CW + n];
            w01 = W[(size_t)(k+1) * CW + n];
            w10 = W[(size_t)(k+8) * CW + n];
            w11 = W[(size_t)(k+9) * CW + n];
        }
        u32 bh0, bl0, bh1, bl1;
        split_pair(w00, w01, bh0, bl0);
        split_pair(w10, w11, bh1, bl1);
        g_Bf[b][i] = make_uint4(bh0, bh1, bl0, bl1);
    }
}

__global__ __launch_bounds__(256) void prep_csr(const int* __restrict__ ei,
                                                const int* __restrict__ eat) {
    __shared__ int cnt[NPG], woff[NPG];
    int g = blockIdx.x, tid = threadIdx.x;
    int ebase = g * EPG;
    if (tid < NPG) cnt[tid] = 0;
    __syncthreads();
    for (int e = tid; e < EPG; e += 256)
        atomicAdd(&cnt[ei[NEDGE + ebase + e] & 63], 1);
    __syncthreads();
    if (tid == 0) {
        int run = 0;
        for (int i = 0; i < NPG; i++) {
            woff[i] = run;
            g_soff[g * NPG + i] = (u16)run;
            run += cnt[i];
        }
    }
    __syncthreads();
    for (int e = tid; e < EPG; e += 256) {
        int sl = ei[ebase + e] & 63;
        int dl = ei[NEDGE + ebase + e] & 63;
        int at = eat[ebase + e];
        int pos = atomicAdd(&woff[dl], 1);
        g_sedge[ebase + pos] = (u8)(sl | (at << 6));
    }
}

// ---------------- K1: GAT1 + (h1 @ c2_w) ----------------
struct K1S {
    float shh[NPG*STR];
    float sh1[NPG*STR];
    float salpha[NPG*ASTR];
    u16   soff[NPG];
    float shs[NPG], shd[NPG];
    float shas[HID], shad[HID], shb[HID];
    float shea[NET];
    int   codes[NPG];
};
__global__ __launch_bounds__(256) void k1(
    const int* __restrict__ x,
    const float* __restrict__ a_s, const float* __restrict__ a_d,
    const float* __restrict__ bias) {
    extern __shared__ char smraw[];
    K1S& S = *(K1S*)smraw;
    int g = blockIdx.x, tid = threadIdx.x;
    int lane = tid & 31, wid = tid >> 5;

    if (tid < HID) { S.shas[tid] = a_s[tid]; S.shad[tid] = a_d[tid]; S.shb[tid] = bias[tid]; }
    if (tid < NET) S.shea[tid] = g_ea[0][tid];
    if (tid < NPG) { S.codes[tid] = x[g * NPG + tid]; S.soff[tid] = g_soff[g * NPG + tid]; }
    for (int i = tid; i < NPG * ASTR; i += 256) S.salpha[i] = 0.f;
    __syncthreads();
    for (int i = tid; i < NPG * 32; i += 256) {
        int r = i >> 5, qq = i & 31;
        *(float4*)&S.shh[r * STR + qq * 4] = ((const float4*)(g_P1 + S.codes[r] * HID))[qq];
    }
    __syncthreads();

    attn_alpha(S.shh, S.salpha, S.soff, g_sedge + g * EPG,
               S.shas, S.shad, S.shea, S.shs, S.shd, tid);
    __syncthreads();

    int rt = wid & 3, ch = wid >> 2;
    int r0 = rt * 16 + (lane >> 2), kc = (lane & 3) * 2;
    float acc[8][4];

    // h1 = relu(alpha @ h + b) -> sh1
    mma_agg(S.salpha, S.shh, wid, lane, acc);
    #pragma unroll
    for (int nt = 0; nt < 8; nt++) {
        int c = ch * 64 + nt * 8 + kc;
        float b0 = S.shb[c], b1v = S.shb[c+1];
        *(float2*)&S.sh1[r0 * STR + c] =
            make_float2(fmaxf(acc[nt][0] + b0, 0.f), fmaxf(acc[nt][1] + b1v, 0.f));
        *(float2*)&S.sh1[(r0 + 8) * STR + c] =
            make_float2(fmaxf(acc[nt][2] + b0, 0.f), fmaxf(acc[nt][3] + b1v, 0.f));
    }
    __syncthreads();

    // g_hw = sh1 @ c2_w
    mma_block(S.sh1, g_Bf[0], wid, lane, acc);
    float* o0 = g_hw + (size_t)(g * NPG + r0) * HID;
    float* o8 = o0 + 8 * (size_t)HID;
    #pragma unroll
    for (int nt = 0; nt < 8; nt++) {
        int c = ch * 64 + nt * 8 + kc;
        *(float2*)(o0 + c) = make_float2(acc[nt][0], acc[nt][1]);
        *(float2*)(o8 + c) = make_float2(acc[nt][2], acc[nt][3]);
    }
}

// ---------------- K2: GAT2 + heads ----------------
struct K2S {
    float shh[NPG*STR];    // input tile; later q
    float sh2[NPG*STR];    // h2
    float sht[NPG*STR];    // alpha matrix during attention; t after
    u16   soff[NPG];
    float shs[NPG], shd[NPG];
    float shas[HID], shad[HID], shb[HID];
    float shb1[HID], sheb1[HID], shew2[HID];
    float shpool[HID], shz[HID];
    float shea[NET];
};
__global__ __launch_bounds__(256) void k2(
    const float* __restrict__ a_s, const float* __restrict__ a_d,
    const float* __restrict__ bias,
    const float* __restrict__ n_b1, const float* __restrict__ n_b2,
    const float* __restrict__ e_b1, const float* __restrict__ e_w2,
    const float* __restrict__ e_b2,
    const float* __restrict__ s_w1, const float* __restrict__ s_b1,
    const float* __restrict__ s_w2, const float* __restrict__ s_b2,
    const int* __restrict__ non_edges,
    float* __restrict__ out) {
    extern __shared__ char smraw[];
    K2S& S = *(K2S*)smraw;
    float* salpha = S.sht;   // alias: alpha lives in sht region during attention
    int g = blockIdx.x, tid = threadIdx.x;
    int lane = tid & 31, wid = tid >> 5;

    if (tid < HID) {
        S.shas[tid] = a_s[tid]; S.shad[tid] = a_d[tid]; S.shb[tid] = bias[tid];
        S.shb1[tid] = n_b1[tid]; S.sheb1[tid] = e_b1[tid]; S.shew2[tid] = e_w2[tid];
        S.shpool[tid] = 0.f;
    }
    if (tid < NET) S.shea[tid] = g_ea[1][tid];
    if (tid < NPG) S.soff[tid] = g_soff[g * NPG + tid];
    for (int i = tid; i < NPG * ASTR; i += 256) salpha[i] = 0.f;
    const float4* src4 = (const float4*)(g_hw + (size_t)g * NPG * HID);
    __syncthreads();
    for (int i = tid; i < NPG * 32; i += 256) {
        int r = i >> 5, qq = i & 31;
        *(float4*)&S.shh[r * STR + qq * 4] = src4[i];
    }
    __syncthreads();

    attn_alpha(S.shh, salpha, S.soff, g_sedge + g * EPG,
               S.shas, S.shad, S.shea, S.shs, S.shd, tid);
    __syncthreads();

    int rt = wid & 3, ch = wid >> 2;
    int r0 = rt * 16 + (lane >> 2), kc = (lane & 3) * 2;
    float acc[8][4];

    // h2 = alpha @ h + b -> sh2 ; pool via smem atomics
    mma_agg(salpha, S.shh, wid, lane, acc);
    #pragma unroll
    for (int nt = 0; nt < 8; nt++) {
        int c = ch * 64 + nt * 8 + kc;
        float b0 = S.shb[c], b1v = S.shb[c+1];
        float v0 = acc[nt][0] + b0, v1 = acc[nt][1] + b1v;
        float v2 = acc[nt][2] + b0, v3 = acc[nt][3] + b1v;
        *(float2*)&S.sh2[r0 * STR + c] = make_float2(v0, v1);
        *(float2*)&S.sh2[(r0 + 8) * STR + c] = make_float2(v2, v3);
        atomicAdd(&S.shpool[c],     v0 + v2);
        atomicAdd(&S.shpool[c + 1], v1 + v3);
    }
    __syncthreads();   // sh2 + pool done; salpha (sht) now dead

    // t = relu(h2 @ n_w1 + b1) -> sht
    mma_block(S.sh2, g_Bf[1], wid, lane, acc);
    #pragma unroll
    for (int nt = 0; nt < 8; nt++) {
        int c = ch * 64 + nt * 8 + kc;
        float b0 = S.shb1[c], b1v = S.shb1[c+1];
        *(float2*)&S.sht[r0 * STR + c] =
            make_float2(fmaxf(acc[nt][0] + b0, 0.f), fmaxf(acc[nt][1] + b1v, 0.f));
        *(float2*)&S.sht[(r0 + 8) * STR + c] =
            make_float2(fmaxf(acc[nt][2] + b0, 0.f), fmaxf(acc[nt][3] + b1v, 0.f));
    }
    // q = h2 @ e_w1 -> shh (input tile dead)
    mma_block(S.sh2, g_Bf[2], wid, lane, acc);
    #pragma unroll
    for (int nt = 0; nt < 8; nt++) {
        int c = ch * 64 + nt * 8 + kc;
        *(float2*)&S.shh[r0 * STR + c] = make_float2(acc[nt][0], acc[nt][1]);
        *(float2*)&S.shh[(r0 + 8) * STR + c] = make_float2(acc[nt][2], acc[nt][3]);
    }
    __syncthreads();

    // addnode = t @ n_w2 + n_b2 -> out (strided)
    mma_block(S.sht, g_Bf[3], wid, lane, acc);
    size_t gbase = (size_t)g * OUTW + 1;
    #pragma unroll
    for (int nt = 0; nt < 8; nt++) {
        int c = ch * 64 + nt * 8 + kc;
        size_t b0p = gbase + (size_t)r0 * NOUT;
        size_t b8p = gbase + (size_t)(r0 + 8) * NOUT;
        if (c < NOUT)     { float bb = n_b2[c];   out[b0p + c]   = acc[nt][0] + bb; out[b8p + c]   = acc[nt][2] + bb; }
        if (c + 1 < NOUT) { float bb = n_b2[c+1]; out[b0p + c+1] = acc[nt][1] + bb; out[b8p + c+1] = acc[nt][3] + bb; }
    }

    // addedge head (q in shh)
    int nebase = g * NEPG;
    float eb2 = e_b2[0];
    for (int ne = wid; ne < NEPG; ne += 8) {
        int u = non_edges[(size_t)(nebase + ne) * 2]     & 63;
        int v = non_edges[(size_t)(nebase + ne) * 2 + 1] & 63;
        float acc2 = 0.f;
        #pragma unroll
        for (int uu = 0; uu < 4; uu++) {
            int c = lane + 32 * uu;
            float tv = S.shh[u * STR + c] + S.shh[v * STR + c] + S.sheb1[c];
            tv = fmaxf(tv, 0.f);
            acc2 += tv * S.shew2[c];
        }
        #pragma unroll
        for (int o = 16; o; o >>= 1) acc2 += __shfl_down_sync(0xffffffffu, acc2, o);
        if (lane == 0) out[(size_t)g * OUTW + 1 + NPG * NOUT + ne] = acc2 + eb2;
    }

    // stop head
    if (tid < HID) {
        float acc3 = s_b1[tid];
        #pragma unroll 8
        for (int k = 0; k < HID; k++) acc3 += S.shpool[k] * s_w1[k * HID + tid];
        S.shz[tid] = fmaxf(acc3, 0.f);
    }
    __syncthreads();
    if (wid == 0) {
        float s_ = 0.f;
        #pragma unroll
        for (int u = 0; u < 4; u++) s_ += S.shz[lane + 32*u] * s_w2[lane + 32*u];
        #pragma unroll
        for (int o = 16; o; o >>= 1) s_ += __shfl_down_sync(0xffffffffu, s_, o);
        if (lane == 0) out[(size_t)g * OUTW] = s_ + s_b2[0];
    }
}

// ---------------- launch ----------------
extern "C" void kernel_launch(void* const* d_in, const int* in_sizes, int n_in,
                              void* d_out, int out_size) {
    const float* node_tab = (const float*)d_in[0];
    const float* edge_tab = (const float*)d_in[1];
    const float* c1_w  = (const float*)d_in[2];
    const float* c1_we = (const float*)d_in[3];
    const float* c1_as = (const float*)d_in[4];
    const float* c1_ad = (const float*)d_in[5];
    const float* c1_ae = (const float*)d_in[6];
    const float* c1_b  = (const float*)d_in[7];
    const float* c2_w  = (const float*)d_in[8];
    const float* c2_we = (const float*)d_in[9];
    const float* c2_as = (const float*)d_in[10];
    const float* c2_ad = (const float*)d_in[11];
    const float* c2_ae = (const float*)d_in[12];
    const float* c2_b  = (const float*)d_in[13];
    const float* s_w1  = (const float*)d_in[14];
    const float* s_b1  = (const float*)d_in[15];
    const float* s_w2  = (const float*)d_in[16];
    const float* s_b2  = (const float*)d_in[17];
    const float* n_w1  = (const float*)d_in[18];
    const float* n_b1  = (const float*)d_in[19];
    const float* n_w2  = (const float*)d_in[20];
    const float* n_b2  = (const float*)d_in[21];
    const float* e_w1  = (const float*)d_in[22];
    const float* e_b1  = (const float*)d_in[23];
    const float* e_w2  = (const float*)d_in[24];
    const float* e_b2  = (const float*)d_in[25];
    const int* x          = (const int*)d_in[26];
    const int* edge_index = (const int*)d_in[27];
    const int* edge_attr  = (const int*)d_in[28];
    const int* non_edges  = (const int*)d_in[29];
    float* out = (float*)d_out;

    cudaFuncSetAttribute(k1, cudaFuncAttributeMaxDynamicSharedMemorySize, (int)sizeof(K1S));
    cudaFuncSetAttribute(k2, cudaFuncAttributeMaxDynamicSharedMemorySize, (int)sizeof(K2S));

    prep_main<<<NCAT + 1, HID>>>(node_tab, edge_tab, c1_w, c1_we, c1_ae, c2_we, c2_ae);
    prep_w<<<4, 256>>>(c2_w, n_w1, e_w1, n_w2);
    prep_csr<<<NB, 256>>>(edge_index, edge_attr);
    k1<<<NB, 256, sizeof(K1S)>>>(x, c1_as, c1_ad, c1_b);
    k2<<<NB, 256, sizeof(K2S)>>>(c2_as, c2_ad, c2_b, n_b1, n_b2, e_b1, e_w2, e_b2,
                                 s_w1, s_b1, s_w2, s_b2, non_edges, out);
}

// round 9
// speedup vs baseline: 1.4556x; 1.4556x over previous
#include <cuda_runtime.h>
#include <cstdint>

#define NB   1024
#define NPG  64
#define EPG  1024
#define NEPG 256
#define NN   (NB*NPG)
#define NEDGE (NB*EPG)
#define EMB  64
#define HID  128
#define NCAT 100
#define NET  4
#define NOUT 101
#define OUTW (1 + NPG*NOUT + NEPG)   // 6721
#define STR  132                      // feature tile stride (floats)

typedef unsigned long long ull;
typedef unsigned int u32;
typedef unsigned short u16;
typedef unsigned char u8;

// ---------------- device scratch ----------------
__device__ float g_P1[NCAT*HID];
__device__ float g_ea[2][NET];
__device__ u8    g_sedge[NEDGE];        // per-graph dst-sorted: src | attr<<6
__device__ u16   g_soff[NB*NPG];        // per-graph CSR start offsets
__device__ uint4 g_Bf[4][4096];         // fragment-order split-bf16 weights: c2_w, n_w1, e_w1, n_w2

// ---------------- helpers ----------------
__device__ __forceinline__ ull pk2(float lo, float hi) {
    ull r; asm("mov.b64 %0, {%1,%2};" : "=l"(r) : "f"(lo), "f"(hi)); return r;
}
__device__ __forceinline__ void fma2(ull& d, ull a, ull b) {
    asm("fma.rn.f32x2 %0, %1, %2, %0;" : "+l"(d) : "l"(a), "l"(b));
}
__device__ __forceinline__ void upk2(ull v, float& lo, float& hi) {
    asm("mov.b64 {%0,%1}, %2;" : "=f"(lo), "=f"(hi) : "l"(v));
}
__device__ __forceinline__ u32 bfpack(float lo, float hi) {
    u32 r; asm("cvt.rn.bf16x2.f32 %0, %1, %2;" : "=r"(r) : "f"(hi), "f"(lo)); return r;
}
__device__ __forceinline__ void split_pair(float x0, float x1, u32& ph, u32& pl) {
    ph = bfpack(x0, x1);
    float h0 = __uint_as_float(ph << 16);
    float h1 = __uint_as_float(ph & 0xFFFF0000u);
    pl = bfpack(x0 - h0, x1 - h1);
}
__device__ __forceinline__ void mma16816(float* c, const u32* a, u32 b0, u32 b1) {
    asm volatile(
        "mma.sync.aligned.m16n8k16.row.col.f32.bf16.bf16.f32 "
        "{%0,%1,%2,%3}, {%4,%5,%6,%7}, {%8,%9}, {%0,%1,%2,%3};"
        : "+f"(c[0]), "+f"(c[1]), "+f"(c[2]), "+f"(c[3])
        : "r"(a[0]), "r"(a[1]), "r"(a[2]), "r"(a[3]), "r"(b0), "r"(b1));
}

// 64x128 @ 128x{128|101} split-bf16; A f32 smem (stride STR), B fragments global.
__device__ __forceinline__ void mma_block(const float* __restrict__ sA,
                                          const uint4* __restrict__ Bf,
                                          int wid, int lane, float acc[8][4]) {
    int rt = wid & 3, ch = wid >> 2;
    int r0 = rt * 16 + (lane >> 2);
    int kc = (lane & 3) * 2;
    const float* pr0 = sA + r0 * STR;
    const float* pr8 = sA + (r0 + 8) * STR;
    #pragma unroll
    for (int nt = 0; nt < 8; nt++)
        #pragma unroll
        for (int j = 0; j < 4; j++) acc[nt][j] = 0.f;
    #pragma unroll
    for (int ks = 0; ks < 8; ks++) {
        int k0 = ks * 16 + kc;
        float2 v00 = *(const float2*)(pr0 + k0);
        float2 v10 = *(const float2*)(pr8 + k0);
        float2 v01 = *(const float2*)(pr0 + k0 + 8);
        float2 v11 = *(const float2*)(pr8 + k0 + 8);
        u32 ah[4], al[4];
        split_pair(v00.x, v00.y, ah[0], al[0]);
        split_pair(v10.x, v10.y, ah[1], al[1]);
        split_pair(v01.x, v01.y, ah[2], al[2]);
        split_pair(v11.x, v11.y, ah[3], al[3]);
        const uint4* bp = Bf + (ks << 9) + (ch << 8) + lane;
        #pragma unroll
        for (int nt = 0; nt < 8; nt++) {
            uint4 b = bp[nt << 5];
            mma16816(acc[nt], ah, b.x, b.y);
            mma16816(acc[nt], al, b.x, b.y);
            mma16816(acc[nt], ah, b.z, b.w);
        }
    }
}

// ---------------- attention: serial aggregation with register softmax ----------------
// tIn -> tOut; CSR (sedge/soff) in smem; pool!=nullptr -> accumulate row sums.
__device__ void attn(const float* __restrict__ tIn, float* __restrict__ tOut,
                     const u8* __restrict__ sedge, const u16* __restrict__ soff,
                     const float* shas, const float* shad, const float* shb,
                     const float* shea, float* shs, float* shd,
                     float* pool, int doRelu, int tid)
{
    int lane = tid & 31, w = tid >> 5;

    // per-node attention scalars s,d
    for (int r = w; r < NPG; r += 8) {
        float ss = 0.f, dd = 0.f;
        #pragma unroll
        for (int u = 0; u < 4; u++) {
            int c = lane + 32 * u;
            float hv = tIn[r * STR + c];
            ss += hv * shas[c]; dd += hv * shad[c];
        }
        #pragma unroll
        for (int o = 16; o; o >>= 1) {
            ss += __shfl_down_sync(0xffffffffu, ss, o);
            dd += __shfl_down_sync(0xffffffffu, dd, o);
        }
        if (lane == 0) { shs[r] = ss; shd[r] = dd; }
    }
    __syncthreads();

    int c0 = lane << 2;
    float pacc[4] = {0.f, 0.f, 0.f, 0.f};
    for (int dl = w; dl < NPG; dl += 8) {
        int st = soff[dl];
        int en = (dl < NPG - 1) ? soff[dl + 1] : EPG;
        float db = shd[dl];
        // pass 1: max
        float m = -1e30f;
        for (int j = st + lane; j < en; j += 32) {
            u32 p = sedge[j];
            float lg = shs[p & 63] + db + shea[p >> 6];
            lg = lg > 0.f ? lg : 0.2f * lg;
            m = fmaxf(m, lg);
        }
        #pragma unroll
        for (int o = 16; o; o >>= 1) m = fmaxf(m, __shfl_xor_sync(0xffffffffu, m, o));
        // pass 2: denominator
        float den = 0.f;
        for (int j = st + lane; j < en; j += 32) {
            u32 p = sedge[j];
            float lg = shs[p & 63] + db + shea[p >> 6];
            lg = lg > 0.f ? lg : 0.2f * lg;
            den += expf(lg - m);
        }
        #pragma unroll
        for (int o = 16; o; o >>= 1) den += __shfl_xor_sync(0xffffffffu, den, o);
        float inv = 1.f / (den + 1e-16f);
        // pass 3: alpha in regs, shfl-broadcast serial aggregation
        ull a0 = 0ull, a1 = 0ull;
        for (int base = st; base < en; base += 32) {
            int j = base + lane;
            float alpha = 0.f; int sl = 0;
            if (j < en) {
                u32 p = sedge[j];
                float lg = shs[p & 63] + db + shea[p >> 6];
                lg = lg > 0.f ? lg : 0.2f * lg;
                alpha = expf(lg - m) * inv;
                sl = p & 63;
            }
            int cn = min(32, en - base);
            for (int jj = 0; jj < cn; jj++) {
                float al = __shfl_sync(0xffffffffu, alpha, jj);
                int s = __shfl_sync(0xffffffffu, sl, jj);
                ull pal = pk2(al, al);
                const ull* hr = (const ull*)&tIn[s * STR + c0];
                fma2(a0, pal, hr[0]);
                fma2(a1, pal, hr[1]);
            }
        }
        float v0, v1, v2, v3;
        upk2(a0, v0, v1); upk2(a1, v2, v3);
        v0 += shb[c0]; v1 += shb[c0+1]; v2 += shb[c0+2]; v3 += shb[c0+3];
        if (doRelu) { v0 = fmaxf(v0,0.f); v1 = fmaxf(v1,0.f); v2 = fmaxf(v2,0.f); v3 = fmaxf(v3,0.f); }
        *(float4*)&tOut[dl * STR + c0] = make_float4(v0, v1, v2, v3);
        if (pool) { pacc[0] += v0; pacc[1] += v1; pacc[2] += v2; pacc[3] += v3; }
    }
    if (pool) {
        atomicAdd(&pool[c0],     pacc[0]);
        atomicAdd(&pool[c0 + 1], pacc[1]);
        atomicAdd(&pool[c0 + 2], pacc[2]);
        atomicAdd(&pool[c0 + 3], pacc[3]);
    }
}

// ---------------- prep kernels ----------------
__global__ void prep_main(const float* __restrict__ node_tab,
                          const float* __restrict__ edge_tab,
                          const float* __restrict__ c1_w,
                          const float* __restrict__ c1_we,
                          const float* __restrict__ c1_ae,
                          const float* __restrict__ c2_we,
                          const float* __restrict__ c2_ae) {
    __shared__ float red[HID];
    int bid = blockIdx.x, tid = threadIdx.x;
    if (bid < NCAT) {
        float acc = 0.f;
        #pragma unroll 8
        for (int k = 0; k < EMB; k++) acc += node_tab[bid*EMB + k] * c1_w[k*HID + tid];
        g_P1[bid*HID + tid] = acc;
    } else {
        for (int combo = 0; combo < 2*NET; combo++) {
            int layer = combo >> 2, t = combo & 3;
            const float* We = layer ? c2_we : c1_we;
            const float* ae = layer ? c2_ae : c1_ae;
            float acc = 0.f;
            #pragma unroll 8
            for (int k = 0; k < EMB; k++) acc += edge_tab[t*EMB + k] * We[k*HID + tid];
            red[tid] = acc * ae[tid];
            __syncthreads();
            if (tid < 32) {
                float s = red[tid] + red[tid+32] + red[tid+64] + red[tid+96];
                #pragma unroll
                for (int o = 16; o; o >>= 1) s += __shfl_down_sync(0xffffffffu, s, o);
                if (tid == 0) g_ea[layer][t] = s;
            }
            __syncthreads();
        }
    }
}

__global__ void prep_w(const float* __restrict__ w0, const float* __restrict__ w1,
                       const float* __restrict__ w2, const float* __restrict__ w3) {
    int b = blockIdx.x, tid = threadIdx.x;
    const float* W = (b == 0) ? w0 : (b == 1) ? w1 : (b == 2) ? w2 : w3;
    int CW = (b == 3) ? NOUT : HID;
    for (int i = tid; i < 4096; i += 256) {
        int ks = i >> 9, rest = i & 511;
        int nt = rest >> 5, l = rest & 31;
        int k = ks * 16 + (l & 3) * 2;
        int n = nt * 8 + (l >> 2);
        float w00=0.f, w01=0.f, w10=0.f, w11=0.f;
        if (n < CW) {
            w00 = W[(size_t)k * CW + n];
            w01 = W[(size_t)(k+1) * CW + n];
            w10 = W[(size_t)(k+8) * CW + n];
            w11 = W[(size_t)(k+9) * CW + n];
        }
        u32 bh0, bl0, bh1, bl1;
        split_pair(w00, w01, bh0, bl0);
        split_pair(w10, w11, bh1, bl1);
        g_Bf[b][i] = make_uint4(bh0, bh1, bl0, bl1);
    }
}

__global__ __launch_bounds__(256) void prep_csr(const int* __restrict__ ei,
                                                const int* __restrict__ eat) {
    __shared__ int cnt[NPG], woff[NPG];
    int g = blockIdx.x, tid = threadIdx.x;
    int ebase = g * EPG;
    if (tid < NPG) cnt[tid] = 0;
    __syncthreads();
    for (int e = tid; e < EPG; e += 256)
        atomicAdd(&cnt[ei[NEDGE + ebase + e] & 63], 1);
    __syncthreads();
    if (tid == 0) {
        int run = 0;
        for (int i = 0; i < NPG; i++) {
            woff[i] = run;
            g_soff[g * NPG + i] = (u16)run;
            run += cnt[i];
        }
    }
    __syncthreads();
    for (int e = tid; e < EPG; e += 256) {
        int sl = ei[ebase + e] & 63;
        int dl = ei[NEDGE + ebase + e] & 63;
        int at = eat[ebase + e];
        int pos = atomicAdd(&woff[dl], 1);
        g_sedge[ebase + pos] = (u8)(sl | (at << 6));
    }
}

// ---------------- mega kernel: whole pipeline per graph ----------------
struct MS {
    float tA[NPG*STR];     // P1 -> hw -> t -> q
    float tB[NPG*STR];     // h1 -> h2
    u8    sedge[EPG];
    u16   soff[NPG];
    float shs[NPG], shd[NPG];
    float shas[HID], shad[HID], shb[HID];
    float sheb1[HID], shew2[HID];
    float pool[HID], z[HID];
    float shea[NET];
    int   codes[NPG];
};

__global__ __launch_bounds__(256, 3) void mega(
    const int* __restrict__ x,
    const float* __restrict__ c1_as, const float* __restrict__ c1_ad, const float* __restrict__ c1_b,
    const float* __restrict__ c2_as, const float* __restrict__ c2_ad, const float* __restrict__ c2_b,
    const float* __restrict__ n_b1, const float* __restrict__ n_b2,
    const float* __restrict__ e_b1, const float* __restrict__ e_w2, const float* __restrict__ e_b2,
    const float* __restrict__ s_w1, const float* __restrict__ s_b1,
    const float* __restrict__ s_w2, const float* __restrict__ s_b2,
    const int* __restrict__ non_edges,
    float* __restrict__ out)
{
    extern __shared__ char smraw[];
    MS& S = *(MS*)smraw;
    int g = blockIdx.x, tid = threadIdx.x;
    int lane = tid & 31, wid = tid >> 5;

    // ---- load structure + layer1 params ----
    if (tid < HID) {
        S.shas[tid] = c1_as[tid]; S.shad[tid] = c1_ad[tid]; S.shb[tid] = c1_b[tid];
        S.sheb1[tid] = e_b1[tid]; S.shew2[tid] = e_w2[tid];
        S.pool[tid] = 0.f;
    }
    if (tid < NET) S.shea[tid] = g_ea[0][tid];
    if (tid < NPG) {
        S.codes[tid] = x[g * NPG + tid];
        S.soff[tid] = g_soff[g * NPG + tid];
    }
    for (int i = tid; i < EPG; i += 256) S.sedge[i] = g_sedge[g * EPG + i];
    __syncthreads();
    // P1 lookup -> tA
    for (int i = tid; i < NPG * 32; i += 256) {
        int r = i >> 5, qq = i & 31;
        *(float4*)&S.tA[r * STR + qq * 4] = ((const float4*)(g_P1 + S.codes[r] * HID))[qq];
    }
    __syncthreads();

    // ---- GAT layer 1: tA -> tB (relu) ----
    attn(S.tA, S.tB, S.sedge, S.soff, S.shas, S.shad, S.shb, S.shea,
         S.shs, S.shd, nullptr, 1, tid);
    __syncthreads();

    int rt = wid & 3, ch = wid >> 2;
    int r0 = rt * 16 + (lane >> 2), kc = (lane & 3) * 2;
    float acc[8][4];

    // ---- hw = h1(tB) @ c2_w -> tA ; also swap in layer2 params ----
    mma_block(S.tB, g_Bf[0], wid, lane, acc);
    __syncthreads();   // everyone done reading tA(P1) already; ensure attn reads done before overwrite
    #pragma unroll
    for (int nt = 0; nt < 8; nt++) {
        int c = ch * 64 + nt * 8 + kc;
        *(float2*)&S.tA[r0 * STR + c] = make_float2(acc[nt][0], acc[nt][1]);
        *(float2*)&S.tA[(r0 + 8) * STR + c] = make_float2(acc[nt][2], acc[nt][3]);
    }
    if (tid < HID) { S.shas[tid] = c2_as[tid]; S.shad[tid] = c2_ad[tid]; S.shb[tid] = c2_b[tid]; }
    if (tid < NET) S.shea[tid] = g_ea[1][tid];
    __syncthreads();

    // ---- GAT layer 2: tA -> tB (h2) + pool ----
    attn(S.tA, S.tB, S.sedge, S.soff, S.shas, S.shad, S.shb, S.shea,
         S.shs, S.shd, S.pool, 0, tid);
    __syncthreads();

    // ---- t = relu(h2 @ n_w1 + n_b1) -> tA ----
    mma_block(S.tB, g_Bf[1], wid, lane, acc);
    __syncthreads();   // attn reads of tA(hw) complete before overwrite
    #pragma unroll
    for (int nt = 0; nt < 8; nt++) {
        int c = ch * 64 + nt * 8 + kc;
        float b0 = n_b1[c], b1v = n_b1[c+1];
        *(float2*)&S.tA[r0 * STR + c] =
            make_float2(fmaxf(acc[nt][0] + b0, 0.f), fmaxf(acc[nt][1] + b1v, 0.f));
        *(float2*)&S.tA[(r0 + 8) * STR + c] =
            make_float2(fmaxf(acc[nt][2] + b0, 0.f), fmaxf(acc[nt][3] + b1v, 0.f));
    }
    __syncthreads();

    // ---- addnode = t(tA) @ n_w2 + n_b2 -> out ----
    mma_block(S.tA, g_Bf[3], wid, lane, acc);
    size_t gbase = (size_t)g * OUTW + 1;
    #pragma unroll
    for (int nt = 0; nt < 8; nt++) {
        int c = ch * 64 + nt * 8 + kc;
        size_t b0p = gbase + (size_t)r0 * NOUT;
        size_t b8p = gbase + (size_t)(r0 + 8) * NOUT;
        if (c < NOUT)     { float bb = n_b2[c];   out[b0p + c]   = acc[nt][0] + bb; out[b8p + c]   = acc[nt][2] + bb; }
        if (c + 1 < NOUT) { float bb = n_b2[c+1]; out[b0p + c+1] = acc[nt][1] + bb; out[b8p + c+1] = acc[nt][3] + bb; }
    }
    __syncthreads();

    // ---- q = h2(tB) @ e_w1 -> tA ----
    mma_block(S.tB, g_Bf[2], wid, lane, acc);
    #pragma unroll
    for (int nt = 0; nt < 8; nt++) {
        int c = ch * 64 + nt * 8 + kc;
        *(float2*)&S.tA[r0 * STR + c] = make_float2(acc[nt][0], acc[nt][1]);
        *(float2*)&S.tA[(r0 + 8) * STR + c] = make_float2(acc[nt][2], acc[nt][3]);
    }
    __syncthreads();

    // ---- addedge head (q in tA) ----
    int nebase = g * NEPG;
    float eb2 = e_b2[0];
    for (int ne = wid; ne < NEPG; ne += 8) {
        int u = non_edges[(size_t)(nebase + ne) * 2]     & 63;
        int v = non_edges[(size_t)(nebase + ne) * 2 + 1] & 63;
        float acc2 = 0.f;
        #pragma unroll
        for (int uu = 0; uu < 4; uu++) {
            int c = lane + 32 * uu;
            float tv = S.tA[u * STR + c] + S.tA[v * STR + c] + S.sheb1[c];
            tv = fmaxf(tv, 0.f);
            acc2 += tv * S.shew2[c];
        }
        #pragma unroll
        for (int o = 16; o; o >>= 1) acc2 += __shfl_down_sync(0xffffffffu, acc2, o);
        if (lane == 0) out[(size_t)g * OUTW + 1 + NPG * NOUT + ne] = acc2 + eb2;
    }

    // ---- stop head ----
    if (tid < HID) {
        float acc3 = s_b1[tid];
        #pragma unroll 8
        for (int k = 0; k < HID; k++) acc3 += S.pool[k] * s_w1[k * HID + tid];
        S.z[tid] = fmaxf(acc3, 0.f);
    }
    __syncthreads();
    if (wid == 0) {
        float s_ = 0.f;
        #pragma unroll
        for (int u = 0; u < 4; u++) s_ += S.z[lane + 32*u] * s_w2[lane + 32*u];
        #pragma unroll
        for (int o = 16; o; o >>= 1) s_ += __shfl_down_sync(0xffffffffu, s_, o);
        if (lane == 0) out[(size_t)g * OUTW] = s_ + s_b2[0];
    }
}

// ---------------- launch ----------------
extern "C" void kernel_launch(void* const* d_in, const int* in_sizes, int n_in,
                              void* d_out, int out_size) {
    const float* node_tab = (const float*)d_in[0];
    const float* edge_tab = (const float*)d_in[1];
    const float* c1_w  = (const float*)d_in[2];
    const float* c1_we = (const float*)d_in[3];
    const float* c1_as = (const float*)d_in[4];
    const float* c1_ad = (const float*)d_in[5];
    const float* c1_ae = (const float*)d_in[6];
    const float* c1_b  = (const float*)d_in[7];
    const float* c2_w  = (const float*)d_in[8];
    const float* c2_we = (const float*)d_in[9];
    const float* c2_as = (const float*)d_in[10];
    const float* c2_ad = (const float*)d_in[11];
    const float* c2_ae = (const float*)d_in[12];
    const float* c2_b  = (const float*)d_in[13];
    const float* s_w1  = (const float*)d_in[14];
    const float* s_b1  = (const float*)d_in[15];
    const float* s_w2  = (const float*)d_in[16];
    const float* s_b2  = (const float*)d_in[17];
    const float* n_w1  = (const float*)d_in[18];
    const float* n_b1  = (const float*)d_in[19];
    const float* n_w2  = (const float*)d_in[20];
    const float* n_b2  = (const float*)d_in[21];
    const float* e_w1  = (const float*)d_in[22];
    const float* e_b1  = (const float*)d_in[23];
    const float* e_w2  = (const float*)d_in[24];
    const float* e_b2  = (const float*)d_in[25];
    const int* x          = (const int*)d_in[26];
    const int* edge_index = (const int*)d_in[27];
    const int* edge_attr  = (const int*)d_in[28];
    const int* non_edges  = (const int*)d_in[29];
    float* out = (float*)d_out;

    cudaFuncSetAttribute(mega, cudaFuncAttributeMaxDynamicSharedMemorySize, (int)sizeof(MS));

    prep_main<<<NCAT + 1, HID>>>(node_tab, edge_tab, c1_w, c1_we, c1_ae, c2_we, c2_ae);
    prep_w<<<4, 256>>>(c2_w, n_w1, e_w1, n_w2);
    prep_csr<<<NB, 256>>>(edge_index, edge_attr);
    mega<<<NB, 256, sizeof(MS)>>>(x, c1_as, c1_ad, c1_b, c2_as, c2_ad, c2_b,
                                  n_b1, n_b2, e_b1, e_w2, e_b2,
                                  s_w1, s_b1, s_w2, s_b2, non_edges, out);
}